// round 3
// baseline (speedup 1.0000x reference)
#include <cuda_runtime.h>

#define FULL 0xffffffffu
typedef unsigned long long u64;

// Packed gate table: per gate 12 f32x2 values (both halves identical):
// [0]=u00r [1]=u00i [2]=-u00i [3]=u01r [4]=u01i [5]=-u01i
// [6]=u10r [7]=u10i [8]=-u10i [9]=u11r [10]=u11i [11]=-u11i
__device__ __align__(16) u64 g_gates2[16 * 12];

// ---- f32x2 helpers (Blackwell packed FP32; FFMA2 only reachable via PTX) ----
__device__ __forceinline__ u64 pk2(float lo, float hi) {
    u64 r; asm("mov.b64 %0, {%1, %2};" : "=l"(r) : "f"(lo), "f"(hi)); return r;
}
__device__ __forceinline__ void upk2(u64 v, float& lo, float& hi) {
    asm("mov.b64 {%0, %1}, %2;" : "=f"(lo), "=f"(hi) : "l"(v));
}
__device__ __forceinline__ u64 fma2(u64 a, u64 b, u64 c) {
    u64 d; asm("fma.rn.f32x2 %0, %1, %2, %3;" : "=l"(d) : "l"(a), "l"(b), "l"(c)); return d;
}
__device__ __forceinline__ u64 mul2(u64 a, u64 b) {
    u64 d; asm("mul.rn.f32x2 %0, %1, %2;" : "=l"(d) : "l"(a), "l"(b)); return d;
}
__device__ __forceinline__ u64 add2(u64 a, u64 b) {
    u64 d; asm("add.rn.f32x2 %0, %1, %2;" : "=l"(d) : "l"(a), "l"(b)); return d;
}
__device__ __forceinline__ u64 neg2(u64 a) { return a ^ 0x8000000080000000ULL; }

__global__ void precompute_gates_kernel(const float* __restrict__ theta) {
    int g = threadIdx.x;
    if (g >= 16) return;
    float phi = theta[g * 3 + 0];
    float th  = theta[g * 3 + 1];
    float om  = theta[g * 3 + 2];
    float st, ct;
    sincosf(0.5f * th, &st, &ct);
    float a = 0.5f * (phi + om);
    float b = 0.5f * (phi - om);
    float sa, ca, sb, cb;
    sincosf(a, &sa, &ca);
    sincosf(b, &sb, &cb);
    float u00r =  ca * ct, u00i = -sa * ct;   // u00 = e^{-ia} ct
    float u01r = -cb * st, u01i = -sb * st;   // u01 = -e^{+ib} st
    float u10r =  cb * st, u10i = -sb * st;   // u10 = e^{-ib} st
    float u11r =  ca * ct, u11i =  sa * ct;   // u11 = e^{+ia} ct
    u64* o = &g_gates2[g * 12];
    o[0]  = pk2(u00r, u00r); o[1]  = pk2(u00i, u00i); o[2]  = pk2(-u00i, -u00i);
    o[3]  = pk2(u01r, u01r); o[4]  = pk2(u01i, u01i); o[5]  = pk2(-u01i, -u01i);
    o[6]  = pk2(u10r, u10r); o[7]  = pk2(u10i, u10i); o[8]  = pk2(-u10i, -u10i);
    o[9]  = pk2(u11r, u11r); o[10] = pk2(u11i, u11i); o[11] = pk2(-u11i, -u11i);
}

__global__ void __launch_bounds__(256)
qsim_kernel(const float* __restrict__ x, float* __restrict__ out, int batch) {
    int gwarp = (int)((blockIdx.x * blockDim.x + threadIdx.x) >> 5);
    int lane = threadIdx.x & 31;
    int s0 = gwarp * 2;
    if (s0 >= batch) return;
    bool hasB = (s0 + 1) < batch;
    int s1 = hasB ? s0 + 1 : s0;

    // ---- angle encoding, two samples packed into f32x2 halves ----
    float xA = x[s0 * 8 + (lane & 7)];
    float xB = x[s1 * 8 + (lane & 7)];
    xA = fminf(1.0f, fmaxf(-1.0f, xA));
    xB = fminf(1.0f, fmaxf(-1.0f, xB));
    float sA, cA, sB, cB;
    sincospif(0.5f * xA, &sA, &cA);
    sincospif(0.5f * xB, &sB, &cB);
    u64 C = pk2(cA, cB), S = pk2(sA, sB);

    // lane factor: qubits 3..7 live in lane bits 0..4
    u64 LF;
    {
        u64 c3 = __shfl_sync(FULL, C, 3), s3 = __shfl_sync(FULL, S, 3);
        LF = (lane & 1) ? s3 : c3;
        #pragma unroll
        for (int q = 4; q < 8; q++) {
            u64 cq = __shfl_sync(FULL, C, q);
            u64 sq = __shfl_sync(FULL, S, q);
            LF = mul2(LF, ((lane >> (q - 3)) & 1) ? sq : cq);
        }
    }
    u64 C0 = __shfl_sync(FULL, C, 0), S0 = __shfl_sync(FULL, S, 0);
    u64 C1 = __shfl_sync(FULL, C, 1), S1 = __shfl_sync(FULL, S, 1);
    u64 C2 = __shfl_sync(FULL, C, 2), S2 = __shfl_sync(FULL, S, 2);

    u64 Ar[8], Ai[8];
    #pragma unroll
    for (int j = 0; j < 8; j++) {
        Ar[j] = mul2(mul2(mul2(LF, (j & 1) ? S0 : C0), (j & 2) ? S1 : C1),
                     (j & 4) ? S2 : C2);
        Ai[j] = 0ULL;
    }

    // CNOT-chain permutation source lanes (applied after layer 0)
    const int sl0 = lane ^ ((lane & 15) << 1);
    const int sl1 = sl0 ^ 1;

    // ---- variational layers ----
    #pragma unroll
    for (int layer = 0; layer < 2; layer++) {
        #pragma unroll
        for (int q = 0; q < 8; q++) {
            const u64* G = &g_gates2[(layer * 8 + q) * 12];
            if (q < 3) {
                u64 U00R = G[0], U00I = G[1], N00I = G[2];
                u64 U01R = G[3], U01I = G[4], N01I = G[5];
                u64 U10R = G[6], U10I = G[7], N10I = G[8];
                u64 U11R = G[9], U11I = G[10], N11I = G[11];
                int m = 1 << q;
                #pragma unroll
                for (int j0 = 0; j0 < 8; j0++) {
                    if (j0 & m) continue;
                    int j1 = j0 | m;
                    u64 a0r = Ar[j0], a0i = Ai[j0];
                    u64 a1r = Ar[j1], a1i = Ai[j1];
                    Ar[j0] = fma2(N01I, a1i, fma2(U01R, a1r, fma2(N00I, a0i, mul2(U00R, a0r))));
                    Ai[j0] = fma2(U01I, a1r, fma2(U01R, a1i, fma2(U00I, a0r, mul2(U00R, a0i))));
                    Ar[j1] = fma2(N11I, a1i, fma2(U11R, a1r, fma2(N10I, a0i, mul2(U10R, a0r))));
                    Ai[j1] = fma2(U11I, a1r, fma2(U11R, a1i, fma2(U10I, a0r, mul2(U10R, a0i))));
                }
            } else {
                // cross-lane: lo lane uses (u00,u01), hi lane uses (u11,u10)
                int pb = 1 << (q - 3);
                bool hi = (lane & pb) != 0;
                u64 VSR = hi ? G[9]  : G[0];
                u64 VSI = hi ? G[10] : G[1];
                u64 NSI = hi ? G[11] : G[2];
                u64 VPR = hi ? G[6]  : G[3];
                u64 VPI = hi ? G[7]  : G[4];
                u64 NPI = hi ? G[8]  : G[5];
                #pragma unroll
                for (int j = 0; j < 8; j++) {
                    u64 Pr = __shfl_xor_sync(FULL, Ar[j], pb);
                    u64 Pi = __shfl_xor_sync(FULL, Ai[j], pb);
                    u64 nr = fma2(NPI, Pi, fma2(VPR, Pr, fma2(NSI, Ai[j], mul2(VSR, Ar[j]))));
                    u64 ni = fma2(VPI, Pr, fma2(VPR, Pi, fma2(VSI, Ar[j], mul2(VSR, Ai[j]))));
                    Ar[j] = nr; Ai[j] = ni;
                }
            }
        }

        if (layer == 0) {
            // full CNOT chain as one lane/reg permutation:
            // dest reg j <- src reg j^((j&3)<<1), src lane = sl0 ^ (j>>2)
            u64 br[8], bi[8];
            br[0] = __shfl_sync(FULL, Ar[0], sl0);  bi[0] = __shfl_sync(FULL, Ai[0], sl0);
            br[1] = __shfl_sync(FULL, Ar[3], sl0);  bi[1] = __shfl_sync(FULL, Ai[3], sl0);
            br[2] = __shfl_sync(FULL, Ar[6], sl0);  bi[2] = __shfl_sync(FULL, Ai[6], sl0);
            br[3] = __shfl_sync(FULL, Ar[5], sl0);  bi[3] = __shfl_sync(FULL, Ai[5], sl0);
            br[4] = __shfl_sync(FULL, Ar[4], sl1);  bi[4] = __shfl_sync(FULL, Ai[4], sl1);
            br[5] = __shfl_sync(FULL, Ar[7], sl1);  bi[5] = __shfl_sync(FULL, Ai[7], sl1);
            br[6] = __shfl_sync(FULL, Ar[2], sl1);  bi[6] = __shfl_sync(FULL, Ai[2], sl1);
            br[7] = __shfl_sync(FULL, Ar[1], sl1);  bi[7] = __shfl_sync(FULL, Ai[1], sl1);
            #pragma unroll
            for (int j = 0; j < 8; j++) { Ar[j] = br[j]; Ai[j] = bi[j]; }
        }
        // layer 1's CNOT chain is folded into the Walsh measurement below
    }

    // ---- measurement: <Z_q> = sum_J (-1)^{parity(J & (2^{q+1}-1))} p[J] ----
    u64 p[8];
    #pragma unroll
    for (int j = 0; j < 8; j++)
        p[j] = fma2(Ai[j], Ai[j], mul2(Ar[j], Ar[j]));

    u64 n1 = neg2(p[1]), n2 = neg2(p[2]), n4 = neg2(p[4]);
    u64 n3 = neg2(p[3]), n5 = neg2(p[5]), n6 = neg2(p[6]), n7 = neg2(p[7]);
    // a  = p0-p1+p2-p3+p4-p5+p6-p7
    u64 a  = add2(add2(add2(p[0], n1), add2(p[2], n3)),
                  add2(add2(p[4], n5), add2(p[6], n7)));
    // b  = p0-p1-p2+p3+p4-p5-p6+p7
    u64 b  = add2(add2(add2(p[0], n1), add2(n2, p[3])),
                  add2(add2(p[4], n5), add2(n6, p[7])));
    // cc = p0-p1-p2+p3-p4+p5+p6-p7
    u64 cc = add2(add2(add2(p[0], n1), add2(n2, p[3])),
                  add2(add2(n4, p[5]), add2(p[6], n7)));

    // e0,e1: plain lane sums; e2..e7: fast Walsh of cc (masks 0,1,3,7,15,31)
    #pragma unroll
    for (int d = 1; d < 32; d <<= 1) {
        a = add2(a, __shfl_xor_sync(FULL, a, d));
        b = add2(b, __shfl_xor_sync(FULL, b, d));
        u64 pv = __shfl_xor_sync(FULL, cc, d);
        u64 sum = add2(cc, pv);
        u64 dif = add2(pv, neg2(cc));
        cc = (lane & d) ? dif : sum;
    }

    float vA, vB;
    if (lane == 0) {
        upk2(a, vA, vB);  out[s0 * 8 + 0] = vA; if (hasB) out[s1 * 8 + 0] = vB;
        upk2(b, vA, vB);  out[s0 * 8 + 1] = vA; if (hasB) out[s1 * 8 + 1] = vB;
        upk2(cc, vA, vB); out[s0 * 8 + 2] = vA; if (hasB) out[s1 * 8 + 2] = vB;
    } else if ((lane & (lane + 1)) == 0) {
        // lanes 1,3,7,15,31 -> qubits 3..7
        int qd = 2 + __popc(lane);
        upk2(cc, vA, vB);
        out[s0 * 8 + qd] = vA; if (hasB) out[s1 * 8 + qd] = vB;
    }
}

extern "C" void kernel_launch(void* const* d_in, const int* in_sizes, int n_in,
                              void* d_out, int out_size) {
    const float* inputs = (const float*)d_in[0];   // [16384, 8] f32
    const float* theta  = (const float*)d_in[1];   // [2, 8, 3]  f32
    float* out = (float*)d_out;                    // [16384, 8] f32

    int batch = in_sizes[0] / 8;

    precompute_gates_kernel<<<1, 16>>>(theta);

    int warps = (batch + 1) / 2;           // 2 samples per warp
    int threads = 256;                      // 8 warps / block
    int blocks = (warps * 32 + threads - 1) / threads;
    qsim_kernel<<<blocks, threads>>>(inputs, out, batch);
}

// round 4
// speedup vs baseline: 1.1393x; 1.1393x over previous
#include <cuda_runtime.h>

#define FULL 0xffffffffu

// theta-derived tables (sample-independent):
// g_ry[16]        : (cos(th/2), sin(th/2)) per gate (2 layers x 8 qubits)
// g_d0[256]       : D_phi(layer0) diagonal, (cos,sin) per basis index
// g_d1[256]       : [D_om(layer0) conjugated through CNOT perm] * D_phi(layer1)
// Index convention: I = (lane<<3)|j ; qubit q<3 -> reg bit q, q>=3 -> lane bit (q-3).
__device__ float2 g_ry[16];
__device__ __align__(16) float2 g_d0[256];
__device__ __align__(16) float2 g_d1[256];

__global__ void precompute_kernel(const float* __restrict__ theta) {
    int I = threadIdx.x;          // 0..255
    if (I < 16) {
        int layer = I >> 3, q = I & 7;
        float th = theta[layer * 24 + q * 3 + 1];
        float s, c;
        sincosf(0.5f * th, &s, &c);
        g_ry[I] = make_float2(c, s);
    }
    // D0: RZ(phi) of layer 0. diag entry: bit=0 -> e^{-i phi/2}, bit=1 -> e^{+i phi/2}
    float a0 = 0.0f;
    #pragma unroll
    for (int q = 0; q < 8; q++) {
        float phi = theta[q * 3 + 0];
        a0 += ((I >> q) & 1) ? 0.5f * phi : -0.5f * phi;
    }
    float sr, cr;
    sincosf(a0, &sr, &cr);
    g_d0[I] = make_float2(cr, sr);

    // D1(K) = e^{i Om0(src(K))} * e^{i Phi1(K)}, src(K) = K ^ ((K & 0x7F) << 1)
    int src = I ^ ((I & 0x7F) << 1);
    float a1 = 0.0f;
    #pragma unroll
    for (int q = 0; q < 8; q++) {
        float om0  = theta[q * 3 + 2];
        float phi1 = theta[24 + q * 3 + 0];
        a1 += ((src >> q) & 1) ? 0.5f * om0  : -0.5f * om0;
        a1 += ((I   >> q) & 1) ? 0.5f * phi1 : -0.5f * phi1;
    }
    sincosf(a1, &sr, &cr);
    g_d1[I] = make_float2(cr, sr);
    // RZ(om) of layer 1 is dropped: it cannot change probabilities.
}

__global__ void __launch_bounds__(256)
qsim_kernel(const float* __restrict__ x, float* __restrict__ out, int batch) {
    int warp = (int)((blockIdx.x * blockDim.x + threadIdx.x) >> 5);
    int lane = threadIdx.x & 31;
    if (warp >= batch) return;

    // ---- angle encoding as a real product state ----
    float xv = x[warp * 8 + (lane & 7)];
    xv = fminf(1.0f, fmaxf(-1.0f, xv));
    float s, c;
    sincospif(0.5f * xv, &s, &c);

    float lf = 1.0f;
    #pragma unroll
    for (int q = 3; q < 8; q++) {
        float cq = __shfl_sync(FULL, c, q);
        float sq = __shfl_sync(FULL, s, q);
        lf *= (((lane >> (q - 3)) & 1) ? sq : cq);
    }
    float c0 = __shfl_sync(FULL, c, 0), s0 = __shfl_sync(FULL, s, 0);
    float c1 = __shfl_sync(FULL, c, 1), s1 = __shfl_sync(FULL, s, 1);
    float c2 = __shfl_sync(FULL, c, 2), s2 = __shfl_sync(FULL, s, 2);

    // real amplitudes, then apply D0 (phi-diagonal of layer 0)
    const float4* d0v = reinterpret_cast<const float4*>(g_d0) + lane * 4;
    float ar[8], ai[8];
    #pragma unroll
    for (int jj = 0; jj < 4; jj++) {
        float4 d = d0v[jj];
        int j0 = 2 * jj, j1 = 2 * jj + 1;
        float r0 = lf * ((j0 & 1) ? s0 : c0) * ((j0 & 2) ? s1 : c1) * ((j0 & 4) ? s2 : c2);
        float r1 = lf * ((j1 & 1) ? s0 : c0) * ((j1 & 2) ? s1 : c1) * ((j1 & 4) ? s2 : c2);
        ar[j0] = r0 * d.x; ai[j0] = r0 * d.y;
        ar[j1] = r1 * d.z; ai[j1] = r1 * d.w;
    }

    // CNOT-chain permutation source lanes (used after layer 0)
    const int sl0 = lane ^ ((lane & 15) << 1);
    const int sl1 = sl0 ^ 1;

    // ---- two layers of REAL RY(theta) gates + merged diagonals ----
    #pragma unroll
    for (int layer = 0; layer < 2; layer++) {
        #pragma unroll
        for (int q = 0; q < 8; q++) {
            float2 g = g_ry[layer * 8 + q];
            float cg = g.x, sg = g.y;
            if (q < 3) {
                int m = 1 << q;
                #pragma unroll
                for (int j0 = 0; j0 < 8; j0++) {
                    if (j0 & m) continue;
                    int j1 = j0 | m;
                    float a0r = ar[j0], a0i = ai[j0];
                    float a1r = ar[j1], a1i = ai[j1];
                    ar[j0] = cg * a0r - sg * a1r;
                    ai[j0] = cg * a0i - sg * a1i;
                    ar[j1] = sg * a0r + cg * a1r;
                    ai[j1] = sg * a0i + cg * a1i;
                }
            } else {
                int pb = 1 << (q - 3);
                // lo lane: new = c*self - s*partner ; hi lane: new = c*self + s*partner
                float ss = (lane & pb) ? sg : -sg;
                #pragma unroll
                for (int j = 0; j < 8; j++) {
                    float pr = __shfl_xor_sync(FULL, ar[j], pb);
                    float pi = __shfl_xor_sync(FULL, ai[j], pb);
                    ar[j] = fmaf(ss, pr, cg * ar[j]);
                    ai[j] = fmaf(ss, pi, cg * ai[j]);
                }
            }
        }

        if (layer == 0) {
            // full CNOT chain as one lane/reg permutation:
            // dest reg j <- src reg j^((j&3)<<1), src lane = sl0 ^ (j>>2)
            float br[8], bi[8];
            br[0] = __shfl_sync(FULL, ar[0], sl0);  bi[0] = __shfl_sync(FULL, ai[0], sl0);
            br[1] = __shfl_sync(FULL, ar[3], sl0);  bi[1] = __shfl_sync(FULL, ai[3], sl0);
            br[2] = __shfl_sync(FULL, ar[6], sl0);  bi[2] = __shfl_sync(FULL, ai[6], sl0);
            br[3] = __shfl_sync(FULL, ar[5], sl0);  bi[3] = __shfl_sync(FULL, ai[5], sl0);
            br[4] = __shfl_sync(FULL, ar[4], sl1);  bi[4] = __shfl_sync(FULL, ai[4], sl1);
            br[5] = __shfl_sync(FULL, ar[7], sl1);  bi[5] = __shfl_sync(FULL, ai[7], sl1);
            br[6] = __shfl_sync(FULL, ar[2], sl1);  bi[6] = __shfl_sync(FULL, ai[2], sl1);
            br[7] = __shfl_sync(FULL, ar[1], sl1);  bi[7] = __shfl_sync(FULL, ai[1], sl1);
            // apply D1 = (om-diag of layer 0 pushed through the perm) * (phi-diag of layer 1)
            const float4* d1v = reinterpret_cast<const float4*>(g_d1) + lane * 4;
            #pragma unroll
            for (int jj = 0; jj < 4; jj++) {
                float4 d = d1v[jj];
                int j0 = 2 * jj, j1 = 2 * jj + 1;
                ar[j0] = d.x * br[j0] - d.y * bi[j0];
                ai[j0] = d.x * bi[j0] + d.y * br[j0];
                ar[j1] = d.z * br[j1] - d.w * bi[j1];
                ai[j1] = d.z * bi[j1] + d.w * br[j1];
            }
        }
        // layer 1: om-diag dropped (no effect on probabilities);
        // its CNOT chain is folded into the Walsh measurement below.
    }

    // ---- measurement: <Z_q> = sum_J (-1)^{parity(J & (2^{q+1}-1))} p[J] ----
    float p[8];
    #pragma unroll
    for (int j = 0; j < 8; j++)
        p[j] = ar[j] * ar[j] + ai[j] * ai[j];

    float a  = (p[0] - p[1]) + (p[2] - p[3]) + (p[4] - p[5]) + (p[6] - p[7]);   // parity(j&1)
    float b  = (p[0] - p[1]) - (p[2] - p[3]) + (p[4] - p[5]) - (p[6] - p[7]);   // parity(j&3)
    float cc = (p[0] - p[1]) - (p[2] - p[3]) - (p[4] - p[5]) + (p[6] - p[7]);   // parity(j&7)

    #pragma unroll
    for (int d = 1; d < 32; d <<= 1) {
        a += __shfl_xor_sync(FULL, a, d);
        b += __shfl_xor_sync(FULL, b, d);
        float pv = __shfl_xor_sync(FULL, cc, d);
        cc = (lane & d) ? (pv - cc) : (cc + pv);
    }

    float* o = out + warp * 8;
    if (lane == 0) {
        o[0] = a;
        o[1] = b;
        o[2] = cc;                       // mask 0
    } else if ((lane & (lane + 1)) == 0) {
        o[2 + __popc(lane)] = cc;        // lanes 1,3,7,15,31 -> qubits 3..7
    }
}

extern "C" void kernel_launch(void* const* d_in, const int* in_sizes, int n_in,
                              void* d_out, int out_size) {
    const float* inputs = (const float*)d_in[0];   // [16384, 8] f32
    const float* theta  = (const float*)d_in[1];   // [2, 8, 3]  f32
    float* out = (float*)d_out;                    // [16384, 8] f32

    int batch = in_sizes[0] / 8;

    precompute_kernel<<<1, 256>>>(theta);

    int threads = 256;                       // 8 warps = 8 samples / block
    int blocks = (batch * 32 + threads - 1) / threads;
    qsim_kernel<<<blocks, threads>>>(inputs, out, batch);
}